// round 2
// baseline (speedup 1.0000x reference)
#include <cuda_runtime.h>
#include <cstdint>

// Problem shape (fixed by dataset)
#define M_DIM 4096
#define K_DIM 4096
#define N_DIM 11008

// ---------------- device scratch (static: no allocations allowed) ----------
__device__ int8_t g_qx[(size_t)M_DIM * K_DIM];          // 16 MB quantized activations
__device__ int    g_rsum[M_DIM];                        // per-row sum of qi
__device__ int8_t g_w[(size_t)N_DIM * K_DIM];           // 45 MB unpacked int4 weights

// ---------------- kernel 1: static fake-quant of x -> int8 + row sums ------
__global__ void quant_kernel(const float* __restrict__ x,
                             const float* __restrict__ clampv) {
    const int m = blockIdx.x;
    const float cv  = clampv[0];
    const float inv = 127.0f / cv;
    const float4* xr = reinterpret_cast<const float4*>(x + (size_t)m * K_DIM);
    char4* qr = reinterpret_cast<char4*>(g_qx + (size_t)m * K_DIM);

    int local = 0;
    for (int i = threadIdx.x; i < K_DIM / 4; i += blockDim.x) {
        float4 v = xr[i];
        int a = __float2int_rn(fminf(fmaxf(v.x, -cv), cv) * inv);
        int b = __float2int_rn(fminf(fmaxf(v.y, -cv), cv) * inv);
        int c = __float2int_rn(fminf(fmaxf(v.z, -cv), cv) * inv);
        int d = __float2int_rn(fminf(fmaxf(v.w, -cv), cv) * inv);
        a = max(-127, min(127, a));
        b = max(-127, min(127, b));
        c = max(-127, min(127, c));
        d = max(-127, min(127, d));
        qr[i] = make_char4((char)a, (char)b, (char)c, (char)d);
        local += a + b + c + d;
    }
    __shared__ int sred[256];
    sred[threadIdx.x] = local;
    __syncthreads();
    for (int s = 128; s > 0; s >>= 1) {
        if (threadIdx.x < s) sred[threadIdx.x] += sred[threadIdx.x + s];
        __syncthreads();
    }
    if (threadIdx.x == 0) g_rsum[m] = sred[0];
}

// ---------------- kernel 2: unpack int4 nibbles -> int8 [N, K] -------------
// qweight flat element p (int32 holding one byte) -> out positions 2p (hi), 2p+1 (lo)
__global__ void unpack_kernel(const int* __restrict__ qw) {
    size_t idx = (size_t)blockIdx.x * blockDim.x + threadIdx.x;  // over N*K/4 words
    const size_t total = (size_t)N_DIM * K_DIM / 4;
    if (idx >= total) return;
    int2 q = *reinterpret_cast<const int2*>(qw + 2 * idx);
    uint32_t b0 = (uint32_t)(q.x >> 4) & 15u;
    uint32_t b1 = (uint32_t)(q.x)      & 15u;
    uint32_t b2 = (uint32_t)(q.y >> 4) & 15u;
    uint32_t b3 = (uint32_t)(q.y)      & 15u;
    reinterpret_cast<uint32_t*>(g_w)[idx] = b0 | (b1 << 8) | (b2 << 16) | (b3 << 24);
}

// ---------------- kernel 3: int8 dp4a GEMM + float epilogue ----------------
// C[m,n] = ascale*scale[n]*(dot - z[n]*rsum[m]) + bias[n]
#define BM 128
#define BN 128
#define BK 64

__global__ __launch_bounds__(256, 2)
void gemm_kernel(const int* __restrict__ qz,
                 const float* __restrict__ sc,
                 const float* __restrict__ bias,
                 const float* __restrict__ clampv,
                 float* __restrict__ C) {
    // k-chunk-major smem: element [kc][m] = 4 consecutive K bytes of row m
    __shared__ uint32_t As[BK / 4][BM];   // 8 KB
    __shared__ uint32_t Bs[BK / 4][BN];   // 8 KB

    const int tid = threadIdx.x;
    const int m0 = blockIdx.y * BM;
    const int n0 = blockIdx.x * BN;
    const int tx = tid & 15;   // 0..15 -> n sub-tile
    const int ty = tid >> 4;   // 0..15 -> m sub-tile

    int acc[8][8];
#pragma unroll
    for (int i = 0; i < 8; i++)
#pragma unroll
        for (int j = 0; j < 8; j++) acc[i][j] = 0;

    for (int k0 = 0; k0 < K_DIM; k0 += BK) {
        // load tiles: 128 rows x 64B each = 512 x 16B chunks per matrix, 2/thread
#pragma unroll
        for (int it = 0; it < 2; it++) {
            int c   = tid + it * 256;
            int row = c & 127;       // lane-contiguous rows -> conflict-free STS
            int seg = c >> 7;        // 0..3 (16B segment within 64B k-slice)
            uint4 va = *reinterpret_cast<const uint4*>(
                g_qx + (size_t)(m0 + row) * K_DIM + k0 + seg * 16);
            As[seg * 4 + 0][row] = va.x;
            As[seg * 4 + 1][row] = va.y;
            As[seg * 4 + 2][row] = va.z;
            As[seg * 4 + 3][row] = va.w;
            uint4 vb = *reinterpret_cast<const uint4*>(
                g_w + (size_t)(n0 + row) * K_DIM + k0 + seg * 16);
            Bs[seg * 4 + 0][row] = vb.x;
            Bs[seg * 4 + 1][row] = vb.y;
            Bs[seg * 4 + 2][row] = vb.z;
            Bs[seg * 4 + 3][row] = vb.w;
        }
        __syncthreads();

#pragma unroll
        for (int kc = 0; kc < BK / 4; kc++) {
            uint32_t a[8], b[8];
            *reinterpret_cast<uint4*>(&a[0]) =
                *reinterpret_cast<const uint4*>(&As[kc][ty * 8]);
            *reinterpret_cast<uint4*>(&a[4]) =
                *reinterpret_cast<const uint4*>(&As[kc][ty * 8 + 4]);
            *reinterpret_cast<uint4*>(&b[0]) =
                *reinterpret_cast<const uint4*>(&Bs[kc][tx * 8]);
            *reinterpret_cast<uint4*>(&b[4]) =
                *reinterpret_cast<const uint4*>(&Bs[kc][tx * 8 + 4]);
#pragma unroll
            for (int i = 0; i < 8; i++)
#pragma unroll
                for (int j = 0; j < 8; j++)
                    acc[i][j] = __dp4a((int)a[i], (int)b[j], acc[i][j]);
        }
        __syncthreads();
    }

    // epilogue
    const float ascale = clampv[0] / 127.0f;
    float sj[8], bj[8];
    int zj[8];
#pragma unroll
    for (int j = 0; j < 8; j++) {
        int n = n0 + tx * 8 + j;
        sj[j] = ascale * sc[n];
        zj[j] = qz[n];
        bj[j] = bias[n];
    }
#pragma unroll
    for (int i = 0; i < 8; i++) {
        int m = m0 + ty * 8 + i;
        int rs = g_rsum[m];
        float out[8];
#pragma unroll
        for (int j = 0; j < 8; j++)
            out[j] = sj[j] * (float)(acc[i][j] - zj[j] * rs) + bj[j];
        float4* cp = reinterpret_cast<float4*>(C + (size_t)m * N_DIM + n0 + tx * 8);
        cp[0] = make_float4(out[0], out[1], out[2], out[3]);
        cp[1] = make_float4(out[4], out[5], out[6], out[7]);
    }
}

// ---------------- launch ---------------------------------------------------
extern "C" void kernel_launch(void* const* d_in, const int* in_sizes, int n_in,
                              void* d_out, int out_size) {
    const float* x      = (const float*)d_in[0];
    const int*   qw     = (const int*)d_in[1];
    const int*   qz     = (const int*)d_in[2];
    const float* sc     = (const float*)d_in[3];
    const float* bias   = (const float*)d_in[4];
    const float* clampv = (const float*)d_in[5];
    float* out = (float*)d_out;

    quant_kernel<<<M_DIM, 256>>>(x, clampv);

    const size_t words = (size_t)N_DIM * K_DIM / 4;
    unpack_kernel<<<(unsigned)((words + 255) / 256), 256>>>(qw);

    dim3 grid(N_DIM / BN, M_DIM / BM);
    gemm_kernel<<<grid, 256>>>(qz, sc, bias, clampv, out);
}

// round 5
// speedup vs baseline: 1.2186x; 1.2186x over previous
#include <cuda_runtime.h>
#include <cstdint>

#define M_DIM 4096
#define K_DIM 4096
#define N_DIM 11008

#define BM 128
#define BN 128
#define BKB 128                 // K bytes (int8 elems) per tile iteration
#define K_ITERS (K_DIM / BKB)   // 32
#define THREADS 256

#define STAGE_BYTES (BM*BKB + BN*BKB)   // 16KB + 16KB = 32KB
#define SMEM_BYTES  (2 * STAGE_BYTES)   // 64KB

#define SWZ(off) ((off) ^ (((off) >> 3) & 0x70))

// ---------------- device scratch ------------------------------------------
__device__ int8_t g_qx[(size_t)M_DIM * K_DIM];   // 16 MB quantized activations
__device__ int8_t g_w[(size_t)N_DIM * K_DIM];    // 45 MB (w - z) weights

__device__ __forceinline__ uint32_t smem_u32(const void* p) {
    uint32_t a;
    asm("{ .reg .u64 t; cvta.to.shared.u64 t, %1; cvt.u32.u64 %0, t; }" : "=r"(a) : "l"(p));
    return a;
}

// ---------------- kernel 1: static fake-quant x -> int8 --------------------
__global__ void quant_kernel(const float* __restrict__ x,
                             const float* __restrict__ clampv) {
    const float cv  = clampv[0];
    const float inv = 127.0f / cv;
    size_t i = (size_t)blockIdx.x * blockDim.x + threadIdx.x;   // over M*K/4
    float4 v = reinterpret_cast<const float4*>(x)[i];
    int a = max(-127, min(127, __float2int_rn(fminf(fmaxf(v.x, -cv), cv) * inv)));
    int b = max(-127, min(127, __float2int_rn(fminf(fmaxf(v.y, -cv), cv) * inv)));
    int c = max(-127, min(127, __float2int_rn(fminf(fmaxf(v.z, -cv), cv) * inv)));
    int d = max(-127, min(127, __float2int_rn(fminf(fmaxf(v.w, -cv), cv) * inv)));
    reinterpret_cast<char4*>(g_qx)[i] = make_char4((char)a, (char)b, (char)c, (char)d);
}

// ---------------- kernel 2: unpack int4 -> int8 (w - z) --------------------
// Each int32 of qweight holds ONE byte: hi nibble -> even k, lo nibble -> odd k.
__global__ void unpack_kernel(const int* __restrict__ qw, const int* __restrict__ qz) {
    size_t idx = (size_t)blockIdx.x * blockDim.x + threadIdx.x;  // over N*K/8
    const int n = (int)(idx >> 9);                               // 512 threads per row
    const int z = qz[n];
    int4 q = reinterpret_cast<const int4*>(qw)[idx * 1];  // 4 int32 at qw + idx*4
    int vals[4] = {q.x, q.y, q.z, q.w};
    int8_t o[8];
#pragma unroll
    for (int t = 0; t < 4; t++) {
        o[2*t]   = (int8_t)(((vals[t] >> 4) & 15) - z);
        o[2*t+1] = (int8_t)((vals[t] & 15) - z);
    }
    reinterpret_cast<uint2*>(g_w)[idx] = *reinterpret_cast<uint2*>(o);
}

// ---------------- kernel 3: int8 tensor-core GEMM (mma.sync) ---------------
__global__ __launch_bounds__(THREADS, 2)
void gemm_kernel(const float* __restrict__ sc,
                 const float* __restrict__ bias,
                 const float* __restrict__ clampv,
                 float* __restrict__ C) {
    extern __shared__ char smem[];
    const uint32_t sbase = smem_u32(smem);
    const int tid  = threadIdx.x;
    const int wid  = tid >> 5;
    const int lane = tid & 31;
    const int m0 = blockIdx.y * BM;
    const int n0 = blockIdx.x * BN;
    const int warp_m = (wid & 3) * 32;    // 4 warps along m
    const int warp_n = (wid >> 2) * 64;   // 2 warps along n

    int acc[2][8][4];
#pragma unroll
    for (int f = 0; f < 2; f++)
#pragma unroll
        for (int j = 0; j < 8; j++)
#pragma unroll
            for (int q = 0; q < 4; q++) acc[f][j][q] = 0;

    const int8_t* gA = g_qx + (size_t)m0 * K_DIM;
    const int8_t* gB = g_w  + (size_t)n0 * K_DIM;

    // per-thread tile-load geometry: chunk c = tid + t*256 -> row c>>3, seg c&7
    const int ld_row = tid >> 3;
    const int ld_seg = tid & 7;

#define LOAD_STAGE(s, k0)                                                        \
    do {                                                                         \
        uint32_t sA = sbase + (s) * STAGE_BYTES;                                 \
        uint32_t sB = sA + BM * BKB;                                             \
        _Pragma("unroll")                                                        \
        for (int t = 0; t < 4; t++) {                                            \
            int row = ld_row + t * 32;                                           \
            uint32_t off = SWZ((uint32_t)(row * 128 + ld_seg * 16));             \
            const int8_t* ga = gA + (size_t)row * K_DIM + (k0) + ld_seg * 16;    \
            asm volatile("cp.async.cg.shared.global [%0], [%1], 16;"             \
                         :: "r"(sA + off), "l"(ga) : "memory");                  \
            const int8_t* gb = gB + (size_t)row * K_DIM + (k0) + ld_seg * 16;    \
            asm volatile("cp.async.cg.shared.global [%0], [%1], 16;"             \
                         :: "r"(sB + off), "l"(gb) : "memory");                  \
        }                                                                        \
        asm volatile("cp.async.commit_group;" ::: "memory");                     \
    } while (0)

    LOAD_STAGE(0, 0);

#pragma unroll 1
    for (int it = 0; it < K_ITERS; it++) {
        if (it + 1 < K_ITERS) {
            LOAD_STAGE((it + 1) & 1, (it + 1) * BKB);
            asm volatile("cp.async.wait_group 1;" ::: "memory");
        } else {
            asm volatile("cp.async.wait_group 0;" ::: "memory");
        }
        __syncthreads();

        const int s = it & 1;
        uint32_t sA = sbase + s * STAGE_BYTES;
        uint32_t sB = sA + BM * BKB;

#pragma unroll
        for (int ks = 0; ks < 4; ks++) {
            uint32_t a[2][4];
#pragma unroll
            for (int f = 0; f < 2; f++) {
                uint32_t off = (uint32_t)((warp_m + f * 16 + ((lane >> 3) & 1) * 8 + (lane & 7)) * 128
                                          + ks * 32 + (lane >> 4) * 16);
                uint32_t ad = sA + SWZ(off);
                asm volatile("ldmatrix.sync.aligned.m8n8.x4.shared.b16 {%0,%1,%2,%3}, [%4];"
                             : "=r"(a[f][0]), "=r"(a[f][1]), "=r"(a[f][2]), "=r"(a[f][3])
                             : "r"(ad));
            }
            uint32_t b[4][4];
#pragma unroll
            for (int p = 0; p < 4; p++) {
                uint32_t off = (uint32_t)((warp_n + p * 16 + (lane >> 4) * 8 + (lane & 7)) * 128
                                          + ks * 32 + ((lane >> 3) & 1) * 16);
                uint32_t ad = sB + SWZ(off);
                asm volatile("ldmatrix.sync.aligned.m8n8.x4.shared.b16 {%0,%1,%2,%3}, [%4];"
                             : "=r"(b[p][0]), "=r"(b[p][1]), "=r"(b[p][2]), "=r"(b[p][3])
                             : "r"(ad));
            }
#pragma unroll
            for (int f = 0; f < 2; f++)
#pragma unroll
                for (int j = 0; j < 8; j++) {
                    asm volatile(
                        "mma.sync.aligned.m16n8k32.row.col.s32.s8.s8.s32 "
                        "{%0,%1,%2,%3}, {%4,%5,%6,%7}, {%8,%9}, {%0,%1,%2,%3};"
                        : "+r"(acc[f][j][0]), "+r"(acc[f][j][1]),
                          "+r"(acc[f][j][2]), "+r"(acc[f][j][3])
                        : "r"(a[f][0]), "r"(a[f][1]), "r"(a[f][2]), "r"(a[f][3]),
                          "r"(b[j >> 1][(j & 1) * 2]), "r"(b[j >> 1][(j & 1) * 2 + 1]));
                }
        }
        __syncthreads();
    }

    // ---- epilogue: out = ascale*scale[n]*acc + bias[n] ----
    const float ascale = clampv[0] * (1.0f / 127.0f);
#pragma unroll
    for (int f = 0; f < 2; f++) {
        int r0 = m0 + warp_m + f * 16 + (lane >> 2);
#pragma unroll
        for (int j = 0; j < 8; j++) {
            int col = n0 + warp_n + j * 8 + (lane & 3) * 2;
            float2 s2 = *reinterpret_cast<const float2*>(sc + col);
            float2 b2 = *reinterpret_cast<const float2*>(bias + col);
            float s0 = ascale * s2.x, s1 = ascale * s2.y;
            float2 o0, o1;
            o0.x = s0 * (float)acc[f][j][0] + b2.x;
            o0.y = s1 * (float)acc[f][j][1] + b2.y;
            o1.x = s0 * (float)acc[f][j][2] + b2.x;
            o1.y = s1 * (float)acc[f][j][3] + b2.y;
            *reinterpret_cast<float2*>(C + (size_t)r0 * N_DIM + col) = o0;
            *reinterpret_cast<float2*>(C + (size_t)(r0 + 8) * N_DIM + col) = o1;
        }
    }
}

// ---------------- launch ---------------------------------------------------
extern "C" void kernel_launch(void* const* d_in, const int* in_sizes, int n_in,
                              void* d_out, int out_size) {
    const float* x      = (const float*)d_in[0];
    const int*   qw     = (const int*)d_in[1];
    const int*   qz     = (const int*)d_in[2];
    const float* sc     = (const float*)d_in[3];
    const float* bias   = (const float*)d_in[4];
    const float* clampv = (const float*)d_in[5];
    float* out = (float*)d_out;

    cudaFuncSetAttribute(gemm_kernel, cudaFuncAttributeMaxDynamicSharedMemorySize, SMEM_BYTES);

    quant_kernel<<<(M_DIM * (K_DIM / 4)) / 256, 256>>>(x, clampv);

    const size_t n_thr = (size_t)N_DIM * K_DIM / 8;
    unpack_kernel<<<(unsigned)(n_thr / 256), 256>>>(qw, qz);

    dim3 grid(N_DIM / BN, M_DIM / BM);
    gemm_kernel<<<grid, THREADS, SMEM_BYTES>>>(sc, bias, clampv, out);
}

// round 9
// speedup vs baseline: 2.1031x; 1.7258x over previous
#include <cuda_runtime.h>
#include <cuda_bf16.h>
#include <cstdint>

#define M_DIM 4096
#define K_DIM 4096
#define N_DIM 11008
#define KW    (K_DIM / 2)       // packed int32 per weight row = 2048

#define BM 128
#define BN 128
#define BK 64                   // K-elems per tile iteration
#define K_ITERS (K_DIM / BK)    // 64
#define THREADS 256

// smem: A bf16 tile 16KB, B bf16 tile 16KB, z floats 512B
#define SM_A      0
#define SM_B      (BM * 128)
#define SM_Z      (SM_B + BN * 128)
#define SMEM_BYTES (SM_Z + BN * 4)

#define SWZ(off) ((off) ^ (((off) >> 3) & 0x70))

// ---------------- device scratch (16 MB only — matches R2's passing size) --
__device__ int8_t g_qx[(size_t)M_DIM * K_DIM];

__device__ __forceinline__ uint32_t smem_u32(const void* p) {
    uint32_t a;
    asm("{ .reg .u64 t; cvta.to.shared.u64 t, %1; cvt.u32.u64 %0, t; }" : "=r"(a) : "l"(p));
    return a;
}

// ---------------- kernel 1: static fake-quant x -> int8 --------------------
__global__ void quant_kernel(const float* __restrict__ x,
                             const float* __restrict__ clampv) {
    const float cv  = clampv[0];
    const float inv = 127.0f / cv;
    size_t i = (size_t)blockIdx.x * blockDim.x + threadIdx.x;   // over M*K/4
    float4 v = reinterpret_cast<const float4*>(x)[i];
    int a = max(-127, min(127, __float2int_rn(fminf(fmaxf(v.x, -cv), cv) * inv)));
    int b = max(-127, min(127, __float2int_rn(fminf(fmaxf(v.y, -cv), cv) * inv)));
    int c = max(-127, min(127, __float2int_rn(fminf(fmaxf(v.z, -cv), cv) * inv)));
    int d = max(-127, min(127, __float2int_rn(fminf(fmaxf(v.w, -cv), cv) * inv)));
    reinterpret_cast<char4*>(g_qx)[i] = make_char4((char)a, (char)b, (char)c, (char)d);
}

// int4 (16 int8 bytes) -> 8 bf16x2 words
__device__ __forceinline__ void cvt_a16(const int4 w, uint32_t o[8]) {
    const int v[4] = {w.x, w.y, w.z, w.w};
#pragma unroll
    for (int t = 0; t < 4; t++) {
        float f0 = (float)((v[t] << 24) >> 24);
        float f1 = (float)((v[t] << 16) >> 24);
        float f2 = (float)((v[t] << 8)  >> 24);
        float f3 = (float)( v[t]        >> 24);
        __nv_bfloat162 p0 = __floats2bfloat162_rn(f0, f1);
        __nv_bfloat162 p1 = __floats2bfloat162_rn(f2, f3);
        o[2*t]   = *reinterpret_cast<uint32_t*>(&p0);
        o[2*t+1] = *reinterpret_cast<uint32_t*>(&p1);
    }
}

// ---------------- kernel 2: fused bf16 GEMM, in-kernel A+B conversion ------
__global__ __launch_bounds__(THREADS, 2)
void gemm_kernel(const int* __restrict__ qw,
                 const int* __restrict__ qz,
                 const float* __restrict__ sc,
                 const float* __restrict__ bias,
                 const float* __restrict__ clampv,
                 float* __restrict__ C) {
    extern __shared__ char smem[];
    const uint32_t sbase = smem_u32(smem);
    const int tid  = threadIdx.x;
    const int wid  = tid >> 5;
    const int lane = tid & 31;
    const int m0 = blockIdx.y * BM;
    const int n0 = blockIdx.x * BN;
    const int warp_m = (wid & 3) * 32;    // 4 warps along m
    const int warp_n = (wid >> 2) * 64;   // 2 warps along n

    if (tid < BN)
        *reinterpret_cast<float*>(smem + SM_Z + tid * 4) = (float)qz[n0 + tid];

    float acc[2][8][4];
#pragma unroll
    for (int f = 0; f < 2; f++)
#pragma unroll
        for (int j = 0; j < 8; j++)
#pragma unroll
            for (int q = 0; q < 4; q++) acc[f][j][q] = 0.0f;

    // A geometry: int8 tile 128 x 64B = 512 x 16B chunks, 2/thread
    const int a_row = tid >> 2;          // 0..63 (+64 for 2nd chunk)
    const int a_seg = tid & 3;           // 16B segment within 64B row-slice
    const int8_t* gA0 = g_qx + (size_t)(m0 + a_row)      * K_DIM + a_seg * 16;
    const int8_t* gA1 = g_qx + (size_t)(m0 + a_row + 64) * K_DIM + a_seg * 16;

    // B geometry: packed int4; row = tid>>1, half = tid&1 (32 k-elems = 16 int32)
    const int b_row  = tid >> 1;
    const int b_half = tid & 1;
    const int* gW = qw + (size_t)(n0 + b_row) * KW + b_half * 16;

    // prefetch iter 0
    int4 awreg[2], bwreg[4];
    awreg[0] = *reinterpret_cast<const int4*>(gA0);
    awreg[1] = *reinterpret_cast<const int4*>(gA1);
#pragma unroll
    for (int q = 0; q < 4; q++)
        bwreg[q] = reinterpret_cast<const int4*>(gW)[q];

    __syncthreads();   // z[] visible
    const float zrow = *reinterpret_cast<const float*>(smem + SM_Z + b_row * 4);

#pragma unroll 1
    for (int it = 0; it < K_ITERS; it++) {
        // ---- convert prefetched A -> smem bf16 ----
        {
            uint32_t o[8];
            cvt_a16(awreg[0], o);
            uint32_t off = (uint32_t)(a_row * 128 + a_seg * 32);
            *reinterpret_cast<uint4*>(smem + SM_A + SWZ(off))      = *reinterpret_cast<uint4*>(&o[0]);
            *reinterpret_cast<uint4*>(smem + SM_A + SWZ(off + 16)) = *reinterpret_cast<uint4*>(&o[4]);
            cvt_a16(awreg[1], o);
            off = (uint32_t)((a_row + 64) * 128 + a_seg * 32);
            *reinterpret_cast<uint4*>(smem + SM_A + SWZ(off))      = *reinterpret_cast<uint4*>(&o[0]);
            *reinterpret_cast<uint4*>(smem + SM_A + SWZ(off + 16)) = *reinterpret_cast<uint4*>(&o[4]);
        }
        // ---- convert prefetched B -> smem bf16 ----
#pragma unroll
        for (int q = 0; q < 4; q++) {
            int v[4] = {bwreg[q].x, bwreg[q].y, bwreg[q].z, bwreg[q].w};
            __nv_bfloat16 o[8];
#pragma unroll
            for (int t = 0; t < 4; t++) {
                o[2*t]   = __float2bfloat16((float)((v[t] >> 4) & 15) - zrow);
                o[2*t+1] = __float2bfloat16((float)(v[t] & 15) - zrow);
            }
            uint32_t off = SWZ((uint32_t)(b_row * 128 + b_half * 64 + q * 16));
            *reinterpret_cast<uint4*>(smem + SM_B + off) = *reinterpret_cast<uint4*>(o);
        }

        // ---- prefetch next iter (LDG latency hides under MMA) ----
        if (it + 1 < K_ITERS) {
            const int knext = (it + 1) * BK;
            awreg[0] = *reinterpret_cast<const int4*>(gA0 + knext);
            awreg[1] = *reinterpret_cast<const int4*>(gA1 + knext);
            const int* gWn = gW + (it + 1) * (BK / 2);
#pragma unroll
            for (int q = 0; q < 4; q++)
                bwreg[q] = reinterpret_cast<const int4*>(gWn)[q];
        }

        __syncthreads();

        const uint32_t sA = sbase + SM_A;
        const uint32_t sB = sbase + SM_B;

#pragma unroll
        for (int ks = 0; ks < 4; ks++) {      // 4 x k16 steps per 128B row
            uint32_t a[2][4];
#pragma unroll
            for (int f = 0; f < 2; f++) {
                uint32_t off = (uint32_t)((warp_m + f * 16 + (lane & 15)) * 128
                                          + ks * 32 + (lane >> 4) * 16);
                asm volatile("ldmatrix.sync.aligned.m8n8.x4.shared.b16 {%0,%1,%2,%3}, [%4];"
                             : "=r"(a[f][0]), "=r"(a[f][1]), "=r"(a[f][2]), "=r"(a[f][3])
                             : "r"(sA + SWZ(off)));
            }
            uint32_t b[4][4];
#pragma unroll
            for (int p = 0; p < 4; p++) {
                uint32_t off = (uint32_t)((warp_n + p * 16 + (lane & 15)) * 128
                                          + ks * 32 + (lane >> 4) * 16);
                asm volatile("ldmatrix.sync.aligned.m8n8.x4.shared.b16 {%0,%1,%2,%3}, [%4];"
                             : "=r"(b[p][0]), "=r"(b[p][1]), "=r"(b[p][2]), "=r"(b[p][3])
                             : "r"(sB + SWZ(off)));
            }
#pragma unroll
            for (int f = 0; f < 2; f++)
#pragma unroll
                for (int j = 0; j < 8; j++) {
                    asm volatile(
                        "mma.sync.aligned.m16n8k16.row.col.f32.bf16.bf16.f32 "
                        "{%0,%1,%2,%3}, {%4,%5,%6,%7}, {%8,%9}, {%0,%1,%2,%3};"
                        : "+f"(acc[f][j][0]), "+f"(acc[f][j][1]),
                          "+f"(acc[f][j][2]), "+f"(acc[f][j][3])
                        : "r"(a[f][0]), "r"(a[f][1]), "r"(a[f][2]), "r"(a[f][3]),
                          "r"(b[j >> 1][j & 1]), "r"(b[j >> 1][(j & 1) + 2]));
                }
        }
        __syncthreads();
    }

    // ---- epilogue: out = ascale*scale[n]*acc + bias[n] ----
    const float ascale = clampv[0] * (1.0f / 127.0f);
#pragma unroll
    for (int f = 0; f < 2; f++) {
        int r0 = m0 + warp_m + f * 16 + (lane >> 2);
#pragma unroll
        for (int j = 0; j < 8; j++) {
            int col = n0 + warp_n + j * 8 + (lane & 3) * 2;
            float2 s2 = *reinterpret_cast<const float2*>(sc + col);
            float2 b2 = *reinterpret_cast<const float2*>(bias + col);
            float s0 = ascale * s2.x, s1 = ascale * s2.y;
            float2 o0, o1;
            o0.x = s0 * acc[f][j][0] + b2.x;
            o0.y = s1 * acc[f][j][1] + b2.y;
            o1.x = s0 * acc[f][j][2] + b2.x;
            o1.y = s1 * acc[f][j][3] + b2.y;
            *reinterpret_cast<float2*>(C + (size_t)r0 * N_DIM + col) = o0;
            *reinterpret_cast<float2*>(C + (size_t)(r0 + 8) * N_DIM + col) = o1;
        }
    }
}

// ---------------- launch ---------------------------------------------------
extern "C" void kernel_launch(void* const* d_in, const int* in_sizes, int n_in,
                              void* d_out, int out_size) {
    const float* x      = (const float*)d_in[0];
    const int*   qw     = (const int*)d_in[1];
    const int*   qz     = (const int*)d_in[2];
    const float* sc     = (const float*)d_in[3];
    const float* bias   = (const float*)d_in[4];
    const float* clampv = (const float*)d_in[5];
    float* out = (float*)d_out;

    cudaFuncSetAttribute(gemm_kernel, cudaFuncAttributeMaxDynamicSharedMemorySize, SMEM_BYTES);

    quant_kernel<<<(M_DIM * (K_DIM / 4)) / 256, 256>>>(x, clampv);

    dim3 grid(N_DIM / BN, M_DIM / BM);
    gemm_kernel<<<grid, THREADS, SMEM_BYTES>>>(qw, qz, sc, bias, clampv, out);
}